// round 1
// baseline (speedup 1.0000x reference)
#include <cuda_runtime.h>
#include <cuda_bf16.h>
#include <stdint.h>

#define GRID_N 256
#define KPOINTS 4000000

// Find idx_right = min(searchsorted(p, v, side='left'), 255) exactly,
// using an analytic seed (uniform grid) corrected against the real axis values.
__device__ __forceinline__ void axis_terms(const float* __restrict__ p, float v,
                                           int& lo, int& hi,
                                           float& dl, float& dr, float& ov) {
    // analytic seed for first i with p[i] >= v
    int g = (int)(v * 255.0f) + 1;
    g = min(max(g, 0), GRID_N - 1);
    // correct downward: while p[g-1] >= v
    while (g > 0 && p[g - 1] >= v) g--;
    // correct upward: while p[g] < v (stop at 255 == clamp)
    while (g < GRID_N - 1 && p[g] < v) g++;
    hi = g;
    lo = max(g - 1, 0);
    dl = fmaxf(v - p[lo], 0.0f);
    dr = fmaxf(p[hi] - v, 0.0f);
    if (dl == 0.0f && dr == 0.0f) { dl = 1.0f; dr = 1.0f; }
    ov = dl + dr;
}

__global__ __launch_bounds__(256)
void trilerp_kernel(const float* __restrict__ x,
                    const float* __restrict__ y,
                    const float* __restrict__ z,
                    const float* __restrict__ px,
                    const float* __restrict__ py,
                    const float* __restrict__ pz,
                    const float* __restrict__ values,
                    float* __restrict__ out,
                    int K) {
    __shared__ float spx[GRID_N], spy[GRID_N], spz[GRID_N];
    // cooperative load of the three 256-float axes
    int t = threadIdx.x;
    if (t < GRID_N) {
        spx[t] = px[t];
        spy[t] = py[t];
        spz[t] = pz[t];
    }
    __syncthreads();

    int i = blockIdx.x * blockDim.x + threadIdx.x;
    if (i >= K) return;

    float vx = x[i], vy = y[i], vz = z[i];

    int xlo, xhi, ylo, yhi, zlo, zhi;
    float dxl, dxr, ovx;
    float dyl, dyr, ovy;
    float dzl, dzr, ovz;
    axis_terms(spx, vx, xlo, xhi, dxl, dxr, ovx);
    axis_terms(spy, vy, ylo, yhi, dyl, dyr, ovy);
    axis_terms(spz, vz, zlo, zhi, dzl, dzr, ovz);

    // values[a][b][c] at a*65536 + b*256 + c ; z is contiguous
    const float* r00 = values + (((size_t)xlo << 8) + ylo) * GRID_N;
    const float* r01 = values + (((size_t)xlo << 8) + yhi) * GRID_N;
    const float* r10 = values + (((size_t)xhi << 8) + ylo) * GRID_N;
    const float* r11 = values + (((size_t)xhi << 8) + yhi) * GRID_N;

    // issue all 8 loads up front for MLP
    float v000 = __ldg(r00 + zlo);
    float v001 = __ldg(r00 + zhi);
    float v010 = __ldg(r01 + zlo);
    float v011 = __ldg(r01 + zhi);
    float v100 = __ldg(r10 + zlo);
    float v101 = __ldg(r10 + zhi);
    float v110 = __ldg(r11 + zlo);
    float v111 = __ldg(r11 + zhi);

    // corner (o0,o1,o2): index = (o?hi:lo), weight = opposite dist
    // onoff=0 -> idx_left, weight = dist_right
    float num =
        v000 * (dxr * dyr * dzr) +
        v001 * (dxr * dyr * dzl) +
        v010 * (dxr * dyl * dzr) +
        v011 * (dxr * dyl * dzl) +
        v100 * (dxl * dyr * dzr) +
        v101 * (dxl * dyr * dzl) +
        v110 * (dxl * dyl * dzr) +
        v111 * (dxl * dyl * dzl);

    out[i] = num / (ovx * ovy * ovz);
}

extern "C" void kernel_launch(void* const* d_in, const int* in_sizes, int n_in,
                              void* d_out, int out_size) {
    const float* x      = (const float*)d_in[0];
    const float* y      = (const float*)d_in[1];
    const float* z      = (const float*)d_in[2];
    const float* px     = (const float*)d_in[3];
    const float* py     = (const float*)d_in[4];
    const float* pz     = (const float*)d_in[5];
    const float* values = (const float*)d_in[6];
    float* out = (float*)d_out;

    int K = in_sizes[0];
    int threads = 256;
    int blocks = (K + threads - 1) / threads;
    trilerp_kernel<<<blocks, threads>>>(x, y, z, px, py, pz, values, out, K);
}